// round 5
// baseline (speedup 1.0000x reference)
#include <cuda_runtime.h>

// Problem shape (fixed by setup_inputs):
//   q,k,v: (8, 256, 96, 96) f32 ; kernel_h, kernel_w: (256, 13) f32 ; out f32 same shape.
// Per (b,c): 4 GEMMs of 96x96x96 + 2 row-softmaxes + banded-Toeplitz add.

#define HW    96
#define PCH   100            // smem row pitch in floats (16B-aligned rows)
#define BUFN  (HW * PCH)     // 9600 floats per buffer
#define KS    13
#define NBUF  5

typedef unsigned long long u64;

__device__ __forceinline__ u64 splat2(float x) {
    u64 r; unsigned u = __float_as_uint(x);
    asm("mov.b64 %0, {%1, %2};" : "=l"(r) : "r"(u), "r"(u));
    return r;
}
__device__ __forceinline__ void unpack2(u64 v, float& x, float& y) {
    unsigned a, b;
    asm("mov.b64 {%0, %1}, %2;" : "=r"(a), "=r"(b) : "l"(v));
    x = __uint_as_float(a); y = __uint_as_float(b);
}
// Packed fp32x2 FMA — the only way to reach full-rate fp32 on sm_103a.
__device__ __forceinline__ void ffma2(u64& c, u64 a, u64 b) {
    asm("fma.rn.f32x2 %0, %1, %2, %0;" : "+l"(c) : "l"(a), "l"(b));
}

// C[m][n] tile (6x6 per thread, 16x16 thread grid) with both operands k-major:
//   C[m][n] = sum_k A[k][m] * B[k][n],  A/B rows contiguous with pitch PCH.
// Accumulators packed in pairs along n.
__device__ __forceinline__ void gemm96(const float* __restrict__ A,
                                       const float* __restrict__ B,
                                       int ty6, int tx6, u64 acc[6][3]) {
#pragma unroll
    for (int i = 0; i < 6; ++i)
#pragma unroll
        for (int j = 0; j < 3; ++j) acc[i][j] = 0ull;

    const float* ap = A + ty6;
    const float* bp = B + tx6;
#pragma unroll 4
    for (int kk = 0; kk < HW; ++kk) {
        u64 bv0 = *reinterpret_cast<const u64*>(bp);       // LDS.64, 8B-aligned (tx6 even, PCH even)
        u64 bv1 = *reinterpret_cast<const u64*>(bp + 2);
        u64 bv2 = *reinterpret_cast<const u64*>(bp + 4);
        u64 as[6];
#pragma unroll
        for (int i = 0; i < 6; ++i) as[i] = splat2(ap[i]);
#pragma unroll
        for (int i = 0; i < 6; ++i) {
            ffma2(acc[i][0], as[i], bv0);
            ffma2(acc[i][1], as[i], bv1);
            ffma2(acc[i][2], as[i], bv2);
        }
        ap += PCH; bp += PCH;
    }
}

// Row softmax (rows = m, across the 16 tx lanes) + Toeplitz band add, store TRANSPOSED
// (dstT[n][m]) so the next GEMM reads it k-major.
__device__ __forceinline__ void softmax_band_storeT(u64 acc[6][3], float* __restrict__ dstT,
                                                    const float* __restrict__ kern,
                                                    int ty6, int tx6) {
#pragma unroll
    for (int i = 0; i < 6; ++i) {
        float s[6];
        unpack2(acc[i][0], s[0], s[1]);
        unpack2(acc[i][1], s[2], s[3]);
        unpack2(acc[i][2], s[4], s[5]);

        float m = s[0];
#pragma unroll
        for (int jj = 1; jj < 6; ++jj) m = fmaxf(m, s[jj]);
#pragma unroll
        for (int d = 8; d >= 1; d >>= 1) m = fmaxf(m, __shfl_xor_sync(0xffffffffu, m, d));

        float sum = 0.f;
#pragma unroll
        for (int jj = 0; jj < 6; ++jj) { s[jj] = __expf(s[jj] - m); sum += s[jj]; }
#pragma unroll
        for (int d = 8; d >= 1; d >>= 1) sum += __shfl_xor_sync(0xffffffffu, sum, d);
        float inv = 1.0f / sum;

        const int rg = ty6 + i;
#pragma unroll
        for (int jj = 0; jj < 6; ++jj) {
            int jg = tx6 + jj;
            int off = jg - rg + 6;                     // ks-1-ks//2 = 6 for ks=13
            float bv = (off >= 0 && off < KS) ? kern[off] : 0.f;
            dstT[jg * PCH + rg] = fmaf(s[jj], inv, bv);
        }
    }
}

extern "C" __global__ void __launch_bounds__(256, 1)
dynconv_attn_kernel(const float* __restrict__ q, const float* __restrict__ k,
                    const float* __restrict__ v, const float* __restrict__ kh,
                    const float* __restrict__ kw, float* __restrict__ out) {
    extern __shared__ float smem[];
    float* b0  = smem;             // Q (natural [h][w])
    float* b1  = b0 + BUFN;        // K (natural)
    float* b2  = b1 + BUFN;        // V (natural)          -> later A_w^T
    float* b3  = b2 + BUFN;        // Q^T                  -> later A_h^T
    float* b4  = b3 + BUFN;        // K^T                  -> later v1^T
    float* skh = b4 + BUFN;        // 13 floats
    float* skw = skh + 16;         // 13 floats

    const int t   = threadIdx.x;
    const int tx6 = (t & 15) * 6;
    const int ty6 = (t >> 4) * 6;
    const int bc  = blockIdx.x;
    const int c   = bc & 255;                      // C = 256
    const size_t base = (size_t)bc * (HW * HW);

    // ---- Load Q,K,V (coalesced float4) + per-channel kernels ----
    {
        const float4* gq = reinterpret_cast<const float4*>(q + base);
        const float4* gk = reinterpret_cast<const float4*>(k + base);
        const float4* gv = reinterpret_cast<const float4*>(v + base);
#pragma unroll
        for (int it = 0; it < 9; ++it) {
            int i4  = t + 256 * it;                // 0..2303
            int row = i4 / 24;
            int col = (i4 - row * 24) * 4;
            *reinterpret_cast<float4*>(b0 + row * PCH + col) = gq[i4];
            *reinterpret_cast<float4*>(b1 + row * PCH + col) = gk[i4];
            *reinterpret_cast<float4*>(b2 + row * PCH + col) = gv[i4];
        }
        if (t < KS)            skh[t]      = kh[c * KS + t];
        else if (t < 2 * KS)   skw[t - KS] = kw[c * KS + (t - KS)];
    }
    __syncthreads();

    // ---- Build Q^T, K^T ----
#pragma unroll
    for (int it = 0; it < 36; ++it) {
        int idx = t + 256 * it;                    // 0..9215
        int r   = idx / HW;
        int cc  = idx - r * HW;
        b3[cc * PCH + r] = b0[r * PCH + cc];
        b4[cc * PCH + r] = b1[r * PCH + cc];
    }
    __syncthreads();

    u64 acc[6][3];

    // ---- G1: S_h[h][j] = sum_w Q^T[w][h] * K^T[w][j] ----
    gemm96(b3, b4, ty6, tx6, acc);
    __syncthreads();                               // all reads of b3/b4 done
    // softmax rows h, + band_h, store A_h^T[j][h] into b3
    softmax_band_storeT(acc, b3, skh, ty6, tx6);
    __syncthreads();

    // ---- G3: v1[h][w] = sum_j A_h^T[j][h] * V[j][w]; store v1^T[w][h] into b4 ----
    gemm96(b3, b2, ty6, tx6, acc);
    {
#pragma unroll
        for (int i = 0; i < 6; ++i)
#pragma unroll
            for (int j2 = 0; j2 < 3; ++j2) {
                float x, y; unpack2(acc[i][j2], x, y);
                int wg = tx6 + 2 * j2;
                b4[(wg)     * PCH + ty6 + i] = x;  // b4 (K^T) dead -> v1^T
                b4[(wg + 1) * PCH + ty6 + i] = y;
            }
    }
    __syncthreads();                               // v1^T visible; all V reads done

    // ---- G2: S_w[w][j] = sum_h Q[h][w] * K[h][j] ----
    gemm96(b0, b1, ty6, tx6, acc);
    // softmax rows w, + band_w, store A_w^T[j][w] into b2 (V dead)
    softmax_band_storeT(acc, b2, skw, ty6, tx6);
    __syncthreads();

    // ---- G4: out[h][w] = sum_j v1^T[j][h] * A_w^T[j][w] ----
    gemm96(b4, b2, ty6, tx6, acc);
    {
        float* o = out + base;
#pragma unroll
        for (int i = 0; i < 6; ++i)
#pragma unroll
            for (int j2 = 0; j2 < 3; ++j2) {
                float2 f; unpack2(acc[i][j2], f.x, f.y);
                *reinterpret_cast<float2*>(o + (ty6 + i) * HW + tx6 + 2 * j2) = f;
            }
    }
}

extern "C" void kernel_launch(void* const* d_in, const int* in_sizes, int n_in,
                              void* d_out, int out_size) {
    const float* q  = (const float*)d_in[0];
    const float* k  = (const float*)d_in[1];
    const float* v  = (const float*)d_in[2];
    const float* kh = (const float*)d_in[3];
    const float* kw = (const float*)d_in[4];
    float* out = (float*)d_out;

    const int nbc = in_sizes[0] / (HW * HW);       // B*C = 2048
    const int smem_bytes = (NBUF * BUFN + 32) * (int)sizeof(float);  // 192128 B

    // Idempotent; correctness run sets it before capture, so a capture-time failure is harmless.
    cudaFuncSetAttribute(dynconv_attn_kernel,
                         cudaFuncAttributeMaxDynamicSharedMemorySize, smem_bytes);

    dynconv_attn_kernel<<<nbc, 256, smem_bytes>>>(q, k, v, kh, kw, out);
}